// round 1
// baseline (speedup 1.0000x reference)
#include <cuda_runtime.h>
#include <cuda_bf16.h>
#include <math.h>

// ---------------------------------------------------------------------------
// GaussianSplattingDecoder: occ[v,c] = sum_g exp(-0.5*mahal)*opacity_g*sem_g[c]
//                                      (masked by dist^2 < R^2) + empty term
// V = 100*100*8 = 80000, N = 2048 gaussians, C = 17 classes.
// Strategy: preprocess gaussians (covinv, opacity-scaled semantics), then
// tile voxel grid 4x4x8 per CTA with conservative AABB culling + deterministic
// compaction. Exact per-voxel radius test preserved inside.
// ---------------------------------------------------------------------------

#define N_GAUSS 2048
#define NUM_CLASSES 17
#define PROP_STRIDE 28      // 11 + 17
#define PREP_STRIDE 32      // padded to 8 float4s
#define RADIUS_SQ 16.0f
#define CULL_MARGIN 0.01f

// Per-gaussian preprocessed data: 32 floats each (256 KB total, L2-resident)
// f4[0] = {mx, my, mz, c00}
// f4[1] = {c01, c02, c11, c12}
// f4[2] = {c22, s0, s1, s2}      (s = opacity * semantics)
// f4[3] = {s3, s4, s5, s6}
// f4[4] = {s7, s8, s9, s10}
// f4[5] = {s11, s12, s13, s14}
// f4[6] = {s15, s16, 0, 0}
__device__ float g_prep[N_GAUSS * PREP_STRIDE];

__device__ __forceinline__ float softplus_stable(float x) {
    // matches jax.nn.softplus = logaddexp(x, 0) = max(x,0) + log1p(exp(-|x|))
    return fmaxf(x, 0.0f) + log1pf(expf(-fabsf(x)));
}

__global__ void prep_kernel(const float* __restrict__ props) {
    int g = blockIdx.x * blockDim.x + threadIdx.x;
    if (g >= N_GAUSS) return;
    const float* p = props + g * PROP_STRIDE;

    float mx = p[0], my = p[1], mz = p[2];

    // scales -> inverse variances
    float s0 = fmaxf(softplus_stable(p[3]), 1e-4f);
    float s1 = fmaxf(softplus_stable(p[4]), 1e-4f);
    float s2 = fmaxf(softplus_stable(p[5]), 1e-4f);
    float a0 = 1.0f / fmaxf(s0 * s0, 1e-8f);
    float a1 = 1.0f / fmaxf(s1 * s1, 1e-8f);
    float a2 = 1.0f / fmaxf(s2 * s2, 1e-8f);

    // quaternion -> rotation matrix
    float qw = p[6], qx = p[7], qy = p[8], qz = p[9];
    float qn = sqrtf(qw * qw + qx * qx + qy * qy + qz * qz);
    float inv_n = 1.0f / fmaxf(qn, 1e-8f);
    qw *= inv_n; qx *= inv_n; qy *= inv_n; qz *= inv_n;

    float R00 = 1.0f - 2.0f * (qy * qy + qz * qz);
    float R01 = 2.0f * (qx * qy - qw * qz);
    float R02 = 2.0f * (qx * qz + qw * qy);
    float R10 = 2.0f * (qx * qy + qw * qz);
    float R11 = 1.0f - 2.0f * (qx * qx + qz * qz);
    float R12 = 2.0f * (qy * qz - qw * qx);
    float R20 = 2.0f * (qx * qz - qw * qy);
    float R21 = 2.0f * (qy * qz + qw * qx);
    float R22 = 1.0f - 2.0f * (qx * qx + qy * qy);

    // covinv = R diag(a) R^T (symmetric; 6 unique entries)
    float c00 = a0 * R00 * R00 + a1 * R01 * R01 + a2 * R02 * R02;
    float c01 = a0 * R00 * R10 + a1 * R01 * R11 + a2 * R02 * R12;
    float c02 = a0 * R00 * R20 + a1 * R01 * R21 + a2 * R02 * R22;
    float c11 = a0 * R10 * R10 + a1 * R11 * R11 + a2 * R12 * R12;
    float c12 = a0 * R10 * R20 + a1 * R11 * R21 + a2 * R12 * R22;
    float c22 = a0 * R20 * R20 + a1 * R21 * R21 + a2 * R22 * R22;

    float opacity = 1.0f / (1.0f + expf(-p[10]));

    float* o = g_prep + g * PREP_STRIDE;
    o[0] = mx; o[1] = my; o[2] = mz; o[3] = c00;
    o[4] = c01; o[5] = c02; o[6] = c11; o[7] = c12;
    o[8] = c22;
#pragma unroll
    for (int c = 0; c < NUM_CLASSES; c++)
        o[9 + c] = opacity * p[11 + c];
    o[26] = 0.0f; o[27] = 0.0f; o[28] = 0.0f;
    o[29] = 0.0f; o[30] = 0.0f; o[31] = 0.0f;
}

// Tile = 4x4x8 voxels, 128 threads (1 voxel/thread). Grid = (25, 25).
__global__ __launch_bounds__(128) void splat_kernel(
    const float* __restrict__ vox_coords, float* __restrict__ out)
{
    const int tid = threadIdx.x;
    const int tx = blockIdx.x * 4;
    const int ty = blockIdx.y * 4;
    const int lx = tid >> 5;          // 0..3
    const int ly = (tid >> 3) & 3;    // 0..3
    const int lz = tid & 7;           // 0..7
    const int vx = tx + lx, vy = ty + ly, vz = lz;
    const int v = (vx * 100 + vy) * 8 + vz;

    const float px = vox_coords[v * 3 + 0];
    const float py = vox_coords[v * 3 + 1];
    const float pz = vox_coords[v * 3 + 2];

    // Tile AABB (analytic linspace; expanded by margin for fp safety)
    const float dxy = 80.0f / 99.0f;
    const float bx0 = -40.0f + tx * dxy - CULL_MARGIN;
    const float bx1 = -40.0f + (tx + 3) * dxy + CULL_MARGIN;
    const float by0 = -40.0f + ty * dxy - CULL_MARGIN;
    const float by1 = -40.0f + (ty + 3) * dxy + CULL_MARGIN;
    const float bz0 = -1.0f - CULL_MARGIN;
    const float bz1 = 5.4f + CULL_MARGIN;

    __shared__ int s_list[N_GAUSS];
    __shared__ int s_warp_sums[4];

    // --- Phase 1: conservative AABB cull, 16 consecutive gaussians/thread ---
    const int gbase = tid * 16;
    unsigned int hitmask = 0;
#pragma unroll 4
    for (int i = 0; i < 16; i++) {
        const float4 p0 = __ldg((const float4*)(g_prep + (gbase + i) * PREP_STRIDE));
        float ex = fmaxf(fmaxf(bx0 - p0.x, p0.x - bx1), 0.0f);
        float ey = fmaxf(fmaxf(by0 - p0.y, p0.y - by1), 0.0f);
        float ez = fmaxf(fmaxf(bz0 - p0.z, p0.z - bz1), 0.0f);
        if (ex * ex + ey * ey + ez * ez < RADIUS_SQ) hitmask |= (1u << i);
    }
    int cnt = __popc(hitmask);

    // Deterministic order-preserving compaction: warp scan + CTA offsets
    const int lane = tid & 31, wid = tid >> 5;
    int incl = cnt;
#pragma unroll
    for (int o = 1; o < 32; o <<= 1) {
        int vsh = __shfl_up_sync(0xffffffffu, incl, o);
        if (lane >= o) incl += vsh;
    }
    if (lane == 31) s_warp_sums[wid] = incl;
    __syncthreads();
    int woff = 0;
#pragma unroll
    for (int w = 0; w < 4; w++) if (w < wid) woff += s_warp_sums[w];
    const int total = s_warp_sums[0] + s_warp_sums[1] + s_warp_sums[2] + s_warp_sums[3];
    int offset = woff + incl - cnt;
    unsigned int m = hitmask;
    while (m) {
        int i = __ffs(m) - 1;
        m &= m - 1;
        s_list[offset++] = gbase + i;
    }
    __syncthreads();

    // --- Phase 2: accumulate surviving gaussians ---
    float acc[NUM_CLASSES];
#pragma unroll
    for (int c = 0; c < NUM_CLASSES; c++) acc[c] = 0.0f;

    for (int k = 0; k < total; k++) {
        const int g = s_list[k];
        const float4* P = (const float4*)(g_prep + g * PREP_STRIDE);
        const float4 p0 = __ldg(P + 0);
        const float4 p1 = __ldg(P + 1);
        const float4 p2 = __ldg(P + 2);

        const float d0 = px - p0.x;
        const float d1 = py - p0.y;
        const float d2 = pz - p0.z;
        const float dist_sq = d0 * d0 + d1 * d1 + d2 * d2;
        const bool inside = dist_sq < RADIUS_SQ;

        if (__any_sync(0xffffffffu, inside)) {
            float mahal = p0.w * d0 * d0 + p1.z * d1 * d1 + p2.x * d2 * d2
                        + 2.0f * (p1.x * d0 * d1 + p1.y * d0 * d2 + p1.w * d1 * d2);
            float w = inside ? __expf(-0.5f * mahal) : 0.0f;

            const float4 s0 = __ldg(P + 3);
            const float4 s1 = __ldg(P + 4);
            const float4 s2 = __ldg(P + 5);
            const float4 s3 = __ldg(P + 6);
            acc[0]  += w * p2.y;  acc[1]  += w * p2.z;  acc[2]  += w * p2.w;
            acc[3]  += w * s0.x;  acc[4]  += w * s0.y;  acc[5]  += w * s0.z;  acc[6]  += w * s0.w;
            acc[7]  += w * s1.x;  acc[8]  += w * s1.y;  acc[9]  += w * s1.z;  acc[10] += w * s1.w;
            acc[11] += w * s2.x;  acc[12] += w * s2.y;  acc[13] += w * s2.z;  acc[14] += w * s2.w;
            acc[15] += w * s3.x;  acc[16] += w * s3.y;
        }
    }

    // --- Empty term: center=(0,0,2.2), empty_inv=(1/1600,1/1600,1/10.24) ---
    {
        const float de0 = px;
        const float de1 = py;
        const float de2 = pz - 2.2f;
        const float me = de0 * de0 * (1.0f / 1600.0f)
                       + de1 * de1 * (1.0f / 1600.0f)
                       + de2 * de2 * (1.0f / 10.24f);
        acc[0] += 0.1f * __expf(-0.5f * me) * 5.0f;
    }

    float* o = out + (size_t)v * NUM_CLASSES;
#pragma unroll
    for (int c = 0; c < NUM_CLASSES; c++) o[c] = acc[c];
}

extern "C" void kernel_launch(void* const* d_in, const int* in_sizes, int n_in,
                              void* d_out, int out_size) {
    const float* props = (const float*)d_in[0];
    const float* vox   = (const float*)d_in[1];
    // Disambiguate by size in case of input-order differences.
    if (n_in >= 2 && in_sizes[0] == 100 * 100 * 8 * 3 &&
        in_sizes[1] == N_GAUSS * PROP_STRIDE) {
        const float* t = props; props = vox; vox = t;
    }
    float* out = (float*)d_out;

    prep_kernel<<<(N_GAUSS + 127) / 128, 128>>>(props);
    splat_kernel<<<dim3(25, 25), 128>>>(vox, out);
}

// round 3
// speedup vs baseline: 1.3031x; 1.3031x over previous
#include <cuda_runtime.h>
#include <cuda_bf16.h>
#include <math.h>

// ---------------------------------------------------------------------------
// GaussianSplattingDecoder: occ[v,c] = sum_g exp(-0.5*mahal)*opacity_g*sem_g[c]
//                                      (masked dist^2 < R^2) + empty term
// V = 100*100*8, N = 2048, C = 17.
// R2: 256-thread CTAs (2 threads/voxel, split survivor list) + smem staging
// of survivors so the inner loop never touches L2.
// ---------------------------------------------------------------------------

#define N_GAUSS 2048
#define NUM_CLASSES 17
#define PROP_STRIDE 28      // 11 + 17
#define PREP_STRIDE 32      // padded to 8 float4s
#define RADIUS_SQ 16.0f
#define CULL_MARGIN 0.01f
#define STAGE_CAP 256       // survivors staged in smem; overflow uses L2 path

__device__ float g_prep[N_GAUSS * PREP_STRIDE];

__device__ __forceinline__ float softplus_stable(float x) {
    return fmaxf(x, 0.0f) + log1pf(expf(-fabsf(x)));
}

__global__ void prep_kernel(const float* __restrict__ props) {
    int g = blockIdx.x * blockDim.x + threadIdx.x;
    if (g >= N_GAUSS) return;
    const float* p = props + g * PROP_STRIDE;

    float mx = p[0], my = p[1], mz = p[2];

    float s0 = fmaxf(softplus_stable(p[3]), 1e-4f);
    float s1 = fmaxf(softplus_stable(p[4]), 1e-4f);
    float s2 = fmaxf(softplus_stable(p[5]), 1e-4f);
    float a0 = 1.0f / fmaxf(s0 * s0, 1e-8f);
    float a1 = 1.0f / fmaxf(s1 * s1, 1e-8f);
    float a2 = 1.0f / fmaxf(s2 * s2, 1e-8f);

    float qw = p[6], qx = p[7], qy = p[8], qz = p[9];
    float qn = sqrtf(qw * qw + qx * qx + qy * qy + qz * qz);
    float inv_n = 1.0f / fmaxf(qn, 1e-8f);
    qw *= inv_n; qx *= inv_n; qy *= inv_n; qz *= inv_n;

    float R00 = 1.0f - 2.0f * (qy * qy + qz * qz);
    float R01 = 2.0f * (qx * qy - qw * qz);
    float R02 = 2.0f * (qx * qz + qw * qy);
    float R10 = 2.0f * (qx * qy + qw * qz);
    float R11 = 1.0f - 2.0f * (qx * qx + qz * qz);
    float R12 = 2.0f * (qy * qz - qw * qx);
    float R20 = 2.0f * (qx * qz - qw * qy);
    float R21 = 2.0f * (qy * qz + qw * qx);
    float R22 = 1.0f - 2.0f * (qx * qx + qy * qy);

    float c00 = a0 * R00 * R00 + a1 * R01 * R01 + a2 * R02 * R02;
    float c01 = a0 * R00 * R10 + a1 * R01 * R11 + a2 * R02 * R12;
    float c02 = a0 * R00 * R20 + a1 * R01 * R21 + a2 * R02 * R22;
    float c11 = a0 * R10 * R10 + a1 * R11 * R11 + a2 * R12 * R12;
    float c12 = a0 * R10 * R20 + a1 * R11 * R21 + a2 * R12 * R22;
    float c22 = a0 * R20 * R20 + a1 * R21 * R21 + a2 * R22 * R22;

    float opacity = 1.0f / (1.0f + expf(-p[10]));

    float* o = g_prep + g * PREP_STRIDE;
    o[0] = mx; o[1] = my; o[2] = mz; o[3] = c00;
    o[4] = c01; o[5] = c02; o[6] = c11; o[7] = c12;
    o[8] = c22;
#pragma unroll
    for (int c = 0; c < NUM_CLASSES; c++)
        o[9 + c] = opacity * p[11 + c];
    o[26] = 0.0f; o[27] = 0.0f; o[28] = 0.0f;
    o[29] = 0.0f; o[30] = 0.0f; o[31] = 0.0f;
}

// Tile = 4x4x8 voxels. 256 threads: tid&127 -> voxel, tid>>7 -> list half.
__global__ __launch_bounds__(256) void splat_kernel(
    const float* __restrict__ vox_coords, float* __restrict__ out)
{
    const int tid = threadIdx.x;
    const int tx = blockIdx.x * 4;
    const int ty = blockIdx.y * 4;
    const int vtid = tid & 127;
    const int half = tid >> 7;
    const int lx = vtid >> 5;          // 0..3
    const int ly = (vtid >> 3) & 3;    // 0..3
    const int lz = vtid & 7;           // 0..7
    const int v = ((tx + lx) * 100 + (ty + ly)) * 8 + lz;

    const float px = vox_coords[v * 3 + 0];
    const float py = vox_coords[v * 3 + 1];
    const float pz = vox_coords[v * 3 + 2];

    const float dxy = 80.0f / 99.0f;
    const float bx0 = -40.0f + tx * dxy - CULL_MARGIN;
    const float bx1 = -40.0f + (tx + 3) * dxy + CULL_MARGIN;
    const float by0 = -40.0f + ty * dxy - CULL_MARGIN;
    const float by1 = -40.0f + (ty + 3) * dxy + CULL_MARGIN;
    const float bz0 = -1.0f - CULL_MARGIN;
    const float bz1 = 5.4f + CULL_MARGIN;

    __shared__ int    s_list[N_GAUSS];
    __shared__ float4 s_stage[STAGE_CAP * 7];
    __shared__ float  s_partial[128 * NUM_CLASSES];
    __shared__ int    s_warp_sums[8];

    // --- Phase 1: conservative AABB cull, 8 consecutive gaussians/thread ---
    const int gbase = tid * 8;
    unsigned int hitmask = 0;
#pragma unroll
    for (int i = 0; i < 8; i++) {
        const float4 p0 = __ldg((const float4*)(g_prep + (gbase + i) * PREP_STRIDE));
        float ex = fmaxf(fmaxf(bx0 - p0.x, p0.x - bx1), 0.0f);
        float ey = fmaxf(fmaxf(by0 - p0.y, p0.y - by1), 0.0f);
        float ez = fmaxf(fmaxf(bz0 - p0.z, p0.z - bz1), 0.0f);
        if (ex * ex + ey * ey + ez * ez < RADIUS_SQ) hitmask |= (1u << i);
    }
    int cnt = __popc(hitmask);

    // Deterministic order-preserving compaction
    const int lane = tid & 31, wid = tid >> 5;
    int incl = cnt;
#pragma unroll
    for (int o = 1; o < 32; o <<= 1) {
        int vsh = __shfl_up_sync(0xffffffffu, incl, o);
        if (lane >= o) incl += vsh;
    }
    if (lane == 31) s_warp_sums[wid] = incl;
    __syncthreads();
    int woff = 0, total = 0;
#pragma unroll
    for (int w = 0; w < 8; w++) {
        int ws = s_warp_sums[w];
        if (w < wid) woff += ws;
        total += ws;
    }
    int offset = woff + incl - cnt;
    unsigned int m = hitmask;
    while (m) {
        int i = __ffs(m) - 1;
        m &= m - 1;
        s_list[offset++] = gbase + i;
    }
    __syncthreads();

    // --- Phase 2: cooperative staging of survivors into smem ---
    const int ncap = min(total, STAGE_CAP);
    for (int k = tid; k < ncap; k += 256) {
        const float4* src = (const float4*)(g_prep + s_list[k] * PREP_STRIDE);
        float4* dst = s_stage + k * 7;
#pragma unroll
        for (int j = 0; j < 7; j++) dst[j] = __ldg(src + j);
    }
    __syncthreads();

    // --- Phase 3: accumulate. half 0 -> [0, mid), half 1 -> [mid, total) ---
    float acc[NUM_CLASSES];
#pragma unroll
    for (int c = 0; c < NUM_CLASSES; c++) acc[c] = 0.0f;

    const int mid = total >> 1;
    const int k0 = half ? mid : 0;
    const int k1 = half ? total : mid;

    // smem path
    const int kc = min(k1, STAGE_CAP);
    for (int k = k0; k < kc; k++) {
        const float4* P = s_stage + k * 7;
        const float4 p0 = P[0];
        const float d0 = px - p0.x;
        const float d1 = py - p0.y;
        const float d2 = pz - p0.z;
        const bool inside = (d0 * d0 + d1 * d1 + d2 * d2) < RADIUS_SQ;
        if (__any_sync(0xffffffffu, inside)) {
            const float4 p1 = P[1];
            const float4 p2 = P[2];
            float mahal = p0.w * d0 * d0 + p1.z * d1 * d1 + p2.x * d2 * d2
                        + 2.0f * (p1.x * d0 * d1 + p1.y * d0 * d2 + p1.w * d1 * d2);
            float w = inside ? __expf(-0.5f * mahal) : 0.0f;
            const float4 s0 = P[3];
            const float4 s1 = P[4];
            const float4 s2 = P[5];
            const float4 s3 = P[6];
            acc[0]  += w * p2.y;  acc[1]  += w * p2.z;  acc[2]  += w * p2.w;
            acc[3]  += w * s0.x;  acc[4]  += w * s0.y;  acc[5]  += w * s0.z;  acc[6]  += w * s0.w;
            acc[7]  += w * s1.x;  acc[8]  += w * s1.y;  acc[9]  += w * s1.z;  acc[10] += w * s1.w;
            acc[11] += w * s2.x;  acc[12] += w * s2.y;  acc[13] += w * s2.z;  acc[14] += w * s2.w;
            acc[15] += w * s3.x;  acc[16] += w * s3.y;
        }
    }
    // L2 overflow path (rare; only if total > STAGE_CAP)
    for (int k = max(k0, STAGE_CAP); k < k1; k++) {
        const float4* P = (const float4*)(g_prep + s_list[k] * PREP_STRIDE);
        const float4 p0 = __ldg(P + 0);
        const float d0 = px - p0.x;
        const float d1 = py - p0.y;
        const float d2 = pz - p0.z;
        const bool inside = (d0 * d0 + d1 * d1 + d2 * d2) < RADIUS_SQ;
        if (__any_sync(0xffffffffu, inside)) {
            const float4 p1 = __ldg(P + 1);
            const float4 p2 = __ldg(P + 2);
            float mahal = p0.w * d0 * d0 + p1.z * d1 * d1 + p2.x * d2 * d2
                        + 2.0f * (p1.x * d0 * d1 + p1.y * d0 * d2 + p1.w * d1 * d2);
            float w = inside ? __expf(-0.5f * mahal) : 0.0f;
            const float4 s0 = __ldg(P + 3);
            const float4 s1 = __ldg(P + 4);
            const float4 s2 = __ldg(P + 5);
            const float4 s3 = __ldg(P + 6);
            acc[0]  += w * p2.y;  acc[1]  += w * p2.z;  acc[2]  += w * p2.w;
            acc[3]  += w * s0.x;  acc[4]  += w * s0.y;  acc[5]  += w * s0.z;  acc[6]  += w * s0.w;
            acc[7]  += w * s1.x;  acc[8]  += w * s1.y;  acc[9]  += w * s1.z;  acc[10] += w * s1.w;
            acc[11] += w * s2.x;  acc[12] += w * s2.y;  acc[13] += w * s2.z;  acc[14] += w * s2.w;
            acc[15] += w * s3.x;  acc[16] += w * s3.y;
        }
    }

    // --- Combine halves (deterministic: half0 + half1 order) ---
    if (half) {
#pragma unroll
        for (int c = 0; c < NUM_CLASSES; c++)
            s_partial[vtid * NUM_CLASSES + c] = acc[c];
    }
    __syncthreads();
    if (!half) {
#pragma unroll
        for (int c = 0; c < NUM_CLASSES; c++)
            acc[c] += s_partial[vtid * NUM_CLASSES + c];

        // Empty term: center=(0,0,2.2), inv=(1/1600,1/1600,1/10.24)
        const float de2 = pz - 2.2f;
        const float me = px * px * (1.0f / 1600.0f)
                       + py * py * (1.0f / 1600.0f)
                       + de2 * de2 * (1.0f / 10.24f);
        acc[0] += 0.1f * __expf(-0.5f * me) * 5.0f;

        float* o = out + (size_t)v * NUM_CLASSES;
#pragma unroll
        for (int c = 0; c < NUM_CLASSES; c++) o[c] = acc[c];
    }
}

extern "C" void kernel_launch(void* const* d_in, const int* in_sizes, int n_in,
                              void* d_out, int out_size) {
    const float* props = (const float*)d_in[0];
    const float* vox   = (const float*)d_in[1];
    if (n_in >= 2 && in_sizes[0] == 100 * 100 * 8 * 3 &&
        in_sizes[1] == N_GAUSS * PROP_STRIDE) {
        const float* t = props; props = vox; vox = t;
    }
    float* out = (float*)d_out;

    prep_kernel<<<(N_GAUSS + 127) / 128, 128>>>(props);
    splat_kernel<<<dim3(25, 25), 256>>>(vox, out);
}